// round 13
// baseline (speedup 1.0000x reference)
#include <cuda_runtime.h>
#include <stdint.h>

#define Bq   4
#define Cq   16
#define Hq   512
#define Wq   512
#define HWq  (Hq * Wq)          // 262144
#define NODES (Bq * HWq)        // 1048576
#define NF_ELEMS (NODES * Cq)   // 16777216
#define SQ2f 1.41421356237f
#define RSTRIP 4
#define STEN_BLOCKS (Hq / RSTRIP)       // 128
#define TRANS_BLOCKS (NODES / 256)      // 4096
#define EDGE_TOTAL   2091012
#define EW_BLOCKS    ((EDGE_TOTAL + 255) / 256)  // 8169
#define ROW0_EDGES   2556
#define ROWI_EDGES   4090
#define LASTROW_BASE (ROW0_EDGES + 510 * ROWI_EDGES)  // 2088456

// Fused kernel, three block roles:
//  [0, 128): 4-row strip stencil. Computes every inter-row diff once
//            (pair-forward), owns its rows' full contiguous edge span, and
//            writes attr = (dist, fdiff) as DENSE coalesced float2 via smem.
//  [128, 4224): BCHW -> (B*H*W, C) transpose.
//  [4224, 12393): edge-writer: e -> (src, dst) analytically, coalesced.
__global__ void __launch_bounds__(256) fused_kernel(
    const float* __restrict__ grid, float* __restrict__ nf,
    float* __restrict__ ei_out, float* __restrict__ attr, int E)
{
    __shared__ float s_dl[RSTRIP + 1][Wq];  // pair p: upper(w) vs lower(w-1)
    __shared__ float s_d [RSTRIP + 1][Wq];  // pair p: upper(w) vs lower(w)
    __shared__ float s_dg[RSTRIP + 1][Wq];  // pair p: upper(w) vs lower(w+1)
    __shared__ float s_r [RSTRIP][Wq];      // row  i: (w) vs (w+1)

    if (blockIdx.x >= STEN_BLOCKS + TRANS_BLOCKS) {
        // ---------------- edge-writer part (ei only) ----------------
        int e = (blockIdx.x - STEN_BLOCKS - TRANS_BLOCKS) * 256 + threadIdx.x;
        if (e >= E) return;

        int h, r;
        if (e < ROW0_EDGES)          { h = 0;   r = e; }
        else if (e >= LASTROW_BASE)  { h = 511; r = e - LASTROW_BASE; }
        else { int t = e - ROW0_EDGES; h = 1 + t / ROWI_EDGES; r = t % ROWI_EDGES; }

        const bool edgeRow = (h == 0) || (h == Hq - 1);
        int w, slot;
        if (edgeRow) {
            if (r < 3)          { w = 0;      slot = r; }
            else if (r >= 2553) { w = Wq - 1; slot = r - 2553; }
            else                { w = 1 + (r - 3) / 5; slot = (r - 3) % 5; }
        } else {
            if (r < 5)          { w = 0;      slot = r; }
            else if (r >= 4085) { w = Wq - 1; slot = r - 4085; }
            else                { w = 1 + (r - 5) / 8; slot = (r - 5) % 8; }
        }

        const bool up_ok = (h > 0), dn_ok = (h < Hq - 1);
        const bool l_ok = (w > 0),  r_ok  = (w < Wq - 1);
        const bool v[8] = { up_ok && l_ok, up_ok, up_ok && r_ok,
                            l_ok, r_ok,
                            dn_ok && l_ok, dn_ok, dn_ok && r_ok };
        const int doff[8] = {-Wq - 1, -Wq, -Wq + 1, -1, 1, Wq - 1, Wq, Wq + 1};

        int k = 0, cnt = 0;
#pragma unroll
        for (int kk = 0; kk < 8; kk++) {
            if (v[kk]) { if (cnt == slot) k = kk; cnt++; }
        }

        int n = h * Wq + w;
        ei_out[e]     = (float)n;
        ei_out[E + e] = (float)(n + doff[k]);
        return;
    }

    if (blockIdx.x >= STEN_BLOCKS) {
        // ---------------- transpose part ----------------
        int node = (blockIdx.x - STEN_BLOCKS) * 256 + threadIdx.x;
        int b  = node >> 18;
        int hw = node & (HWq - 1);
        const float* g = grid + (size_t)b * Cq * HWq + hw;

        float v[Cq];
#pragma unroll
        for (int c = 0; c < Cq; c++) v[c] = g[(size_t)c * HWq];

        float4* dst = (float4*)(nf + (size_t)node * Cq);
#pragma unroll
        for (int i = 0; i < 4; i++)
            dst[i] = make_float4(v[4*i], v[4*i+1], v[4*i+2], v[4*i+3]);
        return;
    }

    // ---------------- strip stencil part ----------------
    const int h0 = blockIdx.x * RSTRIP;
    const int w0 = threadIdx.x * 2;

    // 6 row pointers, rows h0-1 .. h0+4 (clamped; invalid pairs masked later)
    const float* p[RSTRIP + 2];
#pragma unroll
    for (int j = 0; j < RSTRIP + 2; j++) {
        int hj = h0 - 1 + j;
        hj = (hj < 0) ? 0 : ((hj > Hq - 1) ? Hq - 1 : hj);
        p[j] = grid + (size_t)hj * Wq;
    }

    const int xl = (w0 > 0)      ? w0 - 1 : 0;
    const int xr = (w0 + 2 < Wq) ? w0 + 2 : Wq - 1;

    float ar[RSTRIP][2];          // intra-row right
    float adl[RSTRIP + 1][2];     // pair down-left
    float ad [RSTRIP + 1][2];     // pair down
    float adg[RSTRIP + 1][2];     // pair down-right
#pragma unroll
    for (int i = 0; i < RSTRIP; i++) { ar[i][0] = 0; ar[i][1] = 0; }
#pragma unroll
    for (int q = 0; q <= RSTRIP; q++) {
        adl[q][0] = 0; adl[q][1] = 0;
        ad [q][0] = 0; ad [q][1] = 0;
        adg[q][0] = 0; adg[q][1] = 0;
    }

    for (int bc = 0; bc < Bq * Cq; bc++) {
        float2 v[RSTRIP + 2];
        float  lh[RSTRIP + 2], rh[RSTRIP + 2];
#pragma unroll
        for (int j = 0; j < RSTRIP + 2; j++)
            v[j] = *(const float2*)(p[j] + w0);
#pragma unroll
        for (int j = 1; j < RSTRIP + 2; j++) {
            lh[j] = p[j][xl];
            rh[j] = p[j][xr];
        }

#pragma unroll
        for (int i = 0; i < RSTRIP; i++) {      // intra row j = i+1
            ar[i][0] += fabsf(v[i+1].x - v[i+1].y);
            ar[i][1] += fabsf(v[i+1].y - rh[i+1]);
        }
#pragma unroll
        for (int q = 0; q <= RSTRIP; q++) {     // pair (row q, row q+1)
            adl[q][0] += fabsf(v[q].x - lh[q+1]);
            ad [q][0] += fabsf(v[q].x - v[q+1].x);
            adg[q][0] += fabsf(v[q].x - v[q+1].y);
            adl[q][1] += fabsf(v[q].y - v[q+1].x);
            ad [q][1] += fabsf(v[q].y - v[q+1].y);
            adg[q][1] += fabsf(v[q].y - rh[q+1]);
        }
#pragma unroll
        for (int j = 0; j < RSTRIP + 2; j++) p[j] += HWq;
    }

    const float inv = 1.0f / (float)(Bq * Cq);
#pragma unroll
    for (int q = 0; q <= RSTRIP; q++) {
        *(float2*)&s_dl[q][w0] = make_float2(adl[q][0] * inv, adl[q][1] * inv);
        *(float2*)&s_d [q][w0] = make_float2(ad [q][0] * inv, ad [q][1] * inv);
        *(float2*)&s_dg[q][w0] = make_float2(adg[q][0] * inv, adg[q][1] * inv);
    }
#pragma unroll
    for (int i = 0; i < RSTRIP; i++)
        *(float2*)&s_r[i][w0] = make_float2(ar[i][0] * inv, ar[i][1] * inv);
    __syncthreads();

    // ---- dense write of this strip's edge span ----
    const int estart = (h0 == 0) ? 0 : (ROW0_EDGES + (h0 - 1) * ROWI_EDGES);
    const int sz0 = (h0 == 0) ? ROW0_EDGES : ROWI_EDGES;
    const int sz3 = (h0 + RSTRIP - 1 == Hq - 1) ? ROW0_EDGES : ROWI_EDGES;
    const int strip_total = sz0 + 2 * ROWI_EDGES + sz3;

    const float dtab[8] = {SQ2f, 1.0f, SQ2f, 1.0f, 1.0f, SQ2f, 1.0f, SQ2f};

    for (int e = estart + threadIdx.x; e < estart + strip_total; e += 256) {
        int eo = e - estart;
        int i = 0;
        if (eo >= sz0) {
            eo -= sz0; i = 1;
            if (eo >= ROWI_EDGES) {
                eo -= ROWI_EDGES; i = 2;
                if (eo >= ROWI_EDGES) { eo -= ROWI_EDGES; i = 3; }
            }
        }
        const int h = h0 + i;
        const bool edgeRow = (h == 0) || (h == Hq - 1);

        int w, slot;
        if (edgeRow) {
            if (eo < 3)          { w = 0;      slot = eo; }
            else if (eo >= 2553) { w = Wq - 1; slot = eo - 2553; }
            else                 { w = 1 + (eo - 3) / 5; slot = (eo - 3) % 5; }
        } else {
            if (eo < 5)          { w = 0;      slot = eo; }
            else if (eo >= 4085) { w = Wq - 1; slot = eo - 4085; }
            else                 { w = 1 + (eo - 5) / 8; slot = (eo - 5) % 8; }
        }

        const bool up_ok = (h > 0), dn_ok = (h < Hq - 1);
        const bool l_ok = (w > 0),  r_ok  = (w < Wq - 1);
        const bool v[8] = { up_ok && l_ok, up_ok, up_ok && r_ok,
                            l_ok, r_ok,
                            dn_ok && l_ok, dn_ok, dn_ok && r_ok };
        int k = 0, cnt = 0;
#pragma unroll
        for (int kk = 0; kk < 8; kk++) {
            if (v[kk]) { if (cnt == slot) k = kk; cnt++; }
        }

        float fd;
        switch (k) {
            case 0:  fd = s_dg[i][w - 1];     break;  // up-left
            case 1:  fd = s_d [i][w];         break;  // up
            case 2:  fd = s_dl[i][w + 1];     break;  // up-right
            case 3:  fd = s_r [i][w - 1];     break;  // left
            case 4:  fd = s_r [i][w];         break;  // right
            case 5:  fd = s_dl[i + 1][w];     break;  // down-left
            case 6:  fd = s_d [i + 1][w];     break;  // down
            default: fd = s_dg[i + 1][w];     break;  // down-right
        }
        ((float2*)attr)[e] = make_float2(dtab[k], fd);
    }
}

extern "C" void kernel_launch(void* const* d_in, const int* in_sizes, int n_in,
                              void* d_out, int out_size)
{
    const float* grid = (const float*)d_in[0];
    const int E = in_sizes[1] / 2;

    float* out    = (float*)d_out;
    float* nf     = out;                    // [NODES, C]
    float* ei_out = out + NF_ELEMS;         // [2, E] as float
    float* attr   = ei_out + 2 * (size_t)E; // [E, 2]

    fused_kernel<<<STEN_BLOCKS + TRANS_BLOCKS + EW_BLOCKS, 256>>>(
        grid, nf, ei_out, attr, E);
}

// round 14
// speedup vs baseline: 3.5060x; 3.5060x over previous
#include <cuda_runtime.h>
#include <stdint.h>

#define Bq   4
#define Cq   16
#define Hq   512
#define Wq   512
#define HWq  (Hq * Wq)          // 262144
#define NODES (Bq * HWq)        // 1048576
#define NF_ELEMS (NODES * Cq)   // 16777216
#define SQ2f 1.41421356237f
#define STEN_BLOCKS 256                 // 2 rows per block
#define TRANS_BLOCKS (NODES / 256)      // 4096
#define EDGE_TOTAL   2091012
#define EW_BLOCKS    ((EDGE_TOTAL + 255) / 256)  // 8169
#define ROW0_EDGES   2556
#define ROWI_EDGES   4090
#define LASTROW_BASE (ROW0_EDGES + 510 * ROWI_EDGES)  // 2088456

// Fused kernel, three block roles (no smem anywhere):
//  [0, 256): forward-only stencil, 2 rows/block, 4 cols/thread (float4),
//            in-warp halos via 3 shuffles; writes ONLY attr[2e+1].
//  [256, 4352): BCHW -> (B*H*W, C) transpose.
//  [4352, 12521): edge-writer: e -> (src, dst, dist) analytically, coalesced.
__global__ void __launch_bounds__(256) fused_kernel(
    const float* __restrict__ grid, float* __restrict__ nf,
    float* __restrict__ ei_out, float* __restrict__ attr, int E)
{
    if (blockIdx.x >= STEN_BLOCKS + TRANS_BLOCKS) {
        // ---------------- edge-writer part ----------------
        int e = (blockIdx.x - STEN_BLOCKS - TRANS_BLOCKS) * 256 + threadIdx.x;
        if (e >= E) return;

        int h, r;
        if (e < ROW0_EDGES)          { h = 0;   r = e; }
        else if (e >= LASTROW_BASE)  { h = 511; r = e - LASTROW_BASE; }
        else { int t = e - ROW0_EDGES; h = 1 + t / ROWI_EDGES; r = t % ROWI_EDGES; }

        const bool edgeRow = (h == 0) || (h == Hq - 1);
        int w, slot;
        if (edgeRow) {
            if (r < 3)          { w = 0;      slot = r; }
            else if (r >= 2553) { w = Wq - 1; slot = r - 2553; }
            else                { w = 1 + (r - 3) / 5; slot = (r - 3) % 5; }
        } else {
            if (r < 5)          { w = 0;      slot = r; }
            else if (r >= 4085) { w = Wq - 1; slot = r - 4085; }
            else                { w = 1 + (r - 5) / 8; slot = (r - 5) % 8; }
        }

        const bool up_ok = (h > 0), dn_ok = (h < Hq - 1);
        const bool l_ok = (w > 0),  r_ok  = (w < Wq - 1);
        const bool v[8] = { up_ok && l_ok, up_ok, up_ok && r_ok,
                            l_ok, r_ok,
                            dn_ok && l_ok, dn_ok, dn_ok && r_ok };
        const int   doff[8] = {-Wq - 1, -Wq, -Wq + 1, -1, 1, Wq - 1, Wq, Wq + 1};
        const float dtab[8] = {SQ2f, 1.0f, SQ2f, 1.0f, 1.0f, SQ2f, 1.0f, SQ2f};

        int k = 0, cnt = 0;
#pragma unroll
        for (int kk = 0; kk < 8; kk++) {
            if (v[kk]) { if (cnt == slot) k = kk; cnt++; }
        }

        int n = h * Wq + w;
        ei_out[e]     = (float)n;
        ei_out[E + e] = (float)(n + doff[k]);
        attr[2 * e]   = dtab[k];
        return;
    }

    if (blockIdx.x >= STEN_BLOCKS) {
        // ---------------- transpose part ----------------
        int node = (blockIdx.x - STEN_BLOCKS) * 256 + threadIdx.x;
        int b  = node >> 18;
        int hw = node & (HWq - 1);
        const float* g = grid + (size_t)b * Cq * HWq + hw;

        float v[Cq];
#pragma unroll
        for (int c = 0; c < Cq; c++) v[c] = g[(size_t)c * HWq];

        float4* dst = (float4*)(nf + (size_t)node * Cq);
#pragma unroll
        for (int i = 0; i < 4; i++)
            dst[i] = make_float4(v[4*i], v[4*i+1], v[4*i+2], v[4*i+3]);
        return;
    }

    // ---------------- stencil part ----------------
    // 2 rows per block: warps 0-3 -> row h0, warps 4-7 -> row h0+1.
    // Each warp covers a 128-col segment, 4 cols/thread via float4.
    const int wid  = threadIdx.x >> 5;
    const int lane = threadIdx.x & 31;
    const int h    = blockIdx.x * 2 + (wid >> 2);
    const int w0   = (wid & 3) * 128 + lane * 4;

    const int hd = (h < Hq - 1) ? h + 1 : h;
    const float* pc = grid + (size_t)h  * Wq;
    const float* pd = grid + (size_t)hd * Wq;

    const int xr = (w0 + 4 < Wq) ? w0 + 4 : Wq - 1;   // clamped boundary cols
    const int xl = (w0 > 0)      ? w0 - 1 : 0;
    const bool bL = (lane == 0);
    const bool bR = (lane == 31);

    // per-col accumulators: right, down-left, down, down-right
    float ar[4], al[4], ad[4], ag[4];
#pragma unroll
    for (int j = 0; j < 4; j++) { ar[j] = 0; al[j] = 0; ad[j] = 0; ag[j] = 0; }

#pragma unroll 4
    for (int bc = 0; bc < Bq * Cq; bc++) {
        float4 c = *(const float4*)(pc + w0);
        float4 d = *(const float4*)(pd + w0);

        float cr = __shfl_down_sync(0xffffffffu, c.x, 1);  // value at w0+4
        float dl = __shfl_up_sync  (0xffffffffu, d.w, 1);  // value at w0-1
        float dr = __shfl_down_sync(0xffffffffu, d.x, 1);  // value at w0+4
        if (bR) { cr = pc[xr]; dr = pd[xr]; }
        if (bL) { dl = pd[xl]; }

        ar[0] += fabsf(c.x - c.y);
        al[0] += fabsf(c.x - dl);
        ad[0] += fabsf(c.x - d.x);
        ag[0] += fabsf(c.x - d.y);

        ar[1] += fabsf(c.y - c.z);
        al[1] += fabsf(c.y - d.x);
        ad[1] += fabsf(c.y - d.y);
        ag[1] += fabsf(c.y - d.z);

        ar[2] += fabsf(c.z - c.w);
        al[2] += fabsf(c.z - d.y);
        ad[2] += fabsf(c.z - d.z);
        ag[2] += fabsf(c.z - d.w);

        ar[3] += fabsf(c.w - cr);
        al[3] += fabsf(c.w - d.z);
        ad[3] += fabsf(c.w - d.w);
        ag[3] += fabsf(c.w - dr);

        pc += HWq; pd += HWq;
    }

    const int  rowbase  = (h == 0) ? 0 : (ROW0_EDGES + ROWI_EDGES * (h - 1));
    const int  rowbase2 = ROW0_EDGES + ROWI_EDGES * h;        // rowbase(h+1)
    const bool edgeRow  = (h == 0) || (h == Hq - 1);
    const bool edgeRow2 = (h + 1 == Hq - 1);
    const bool up_ok = (h > 0), dn_ok = (h < Hq - 1);
    const float inv = 1.0f / (float)(Bq * Cq);

#pragma unroll
    for (int j = 0; j < 4; j++) {
        const int w = w0 + j;
        const bool l_ok = (w > 0), r_ok = (w < Wq - 1);

        const float fr = ar[j] * inv;
        const float fl = al[j] * inv;
        const float fd = ad[j] * inv;
        const float fg = ag[j] * inv;

        const int Pn = rowbase + ((w == 0) ? 0 : (edgeRow ? (3 + 5 * (w - 1))
                                                          : (5 + 8 * (w - 1))));
        const int upc   = up_ok ? (1 + (int)l_ok + (int)r_ok) : 0;
        const int slot4 = upc + (int)l_ok;
        const int slot5 = slot4 + (int)r_ok;
        const int slot6 = slot5 + (int)(dn_ok && l_ok);
        const int slot7 = slot6 + (int)dn_ok;

        if (r_ok) {  // right + its reverse (left of (h,w+1))
            attr[2 * (Pn + slot4) + 1] = fr;
            int wm = w + 1;
            int Pm = rowbase + (edgeRow ? (3 + 5 * (wm - 1)) : (5 + 8 * (wm - 1)));
            int sl = up_ok ? (2 + (int)(wm < Wq - 1)) : 0;
            attr[2 * (Pm + sl) + 1] = fr;
        }
        if (dn_ok) {
            if (l_ok) {  // down-left + reverse (up-right of (h+1,w-1))
                attr[2 * (Pn + slot5) + 1] = fl;
                int wm = w - 1;
                int Pm = rowbase2 + ((wm == 0) ? 0 : (edgeRow2 ? (3 + 5 * (wm - 1))
                                                               : (5 + 8 * (wm - 1))));
                attr[2 * (Pm + 1 + (int)(wm > 0)) + 1] = fl;
            }
            {            // down + reverse (up of (h+1,w))
                attr[2 * (Pn + slot6) + 1] = fd;
                int Pm = rowbase2 + ((w == 0) ? 0 : (edgeRow2 ? (3 + 5 * (w - 1))
                                                              : (5 + 8 * (w - 1))));
                attr[2 * (Pm + (int)l_ok) + 1] = fd;
            }
            if (r_ok) {  // down-right + reverse (up-left of (h+1,w+1))
                attr[2 * (Pn + slot7) + 1] = fg;
                int wm = w + 1;
                int Pm = rowbase2 + (edgeRow2 ? (3 + 5 * (wm - 1)) : (5 + 8 * (wm - 1)));
                attr[2 * Pm + 1] = fg;
            }
        }
    }
}

extern "C" void kernel_launch(void* const* d_in, const int* in_sizes, int n_in,
                              void* d_out, int out_size)
{
    const float* grid = (const float*)d_in[0];
    const int E = in_sizes[1] / 2;

    float* out    = (float*)d_out;
    float* nf     = out;                    // [NODES, C]
    float* ei_out = out + NF_ELEMS;         // [2, E] as float
    float* attr   = ei_out + 2 * (size_t)E; // [E, 2]

    fused_kernel<<<STEN_BLOCKS + TRANS_BLOCKS + EW_BLOCKS, 256>>>(
        grid, nf, ei_out, attr, E);
}

// round 17
// speedup vs baseline: 3.6701x; 1.0468x over previous
#include <cuda_runtime.h>
#include <stdint.h>

#define Bq   4
#define Cq   16
#define Hq   512
#define Wq   512
#define HWq  (Hq * Wq)          // 262144
#define NODES (Bq * HWq)        // 1048576
#define NF_ELEMS (NODES * Cq)   // 16777216
#define SQ2f 1.41421356237f
#define ATTR_BLOCKS 512
#define TRANS_BLOCKS (NODES / 256)     // 4096
#define EDGE_TOTAL   2091012
#define EW_BLOCKS    ((EDGE_TOTAL + 255) / 256)  // 8169
#define ROW0_EDGES   2556
#define ROWI_EDGES   4090
#define LASTROW_BASE (ROW0_EDGES + 510 * ROWI_EDGES)  // 2088456

// Forward-direction feature diffs, node-dense: [node][right, down-left, down, down-right]
__device__ float g_scratch[(size_t)HWq * 4];

// Kernel 1: blocks [0,512): forward-only row stencil (R11 load pattern),
// epilogue = 2 dense float4 stores into g_scratch. Blocks [512,4608): transpose.
__global__ void __launch_bounds__(256) k1_stencil_transpose(
    const float* __restrict__ grid, float* __restrict__ nf)
{
    if (blockIdx.x >= ATTR_BLOCKS) {
        // ---------------- transpose part ----------------
        int node = (blockIdx.x - ATTR_BLOCKS) * 256 + threadIdx.x;
        int b  = node >> 18;
        int hw = node & (HWq - 1);
        const float* g = grid + (size_t)b * Cq * HWq + hw;

        float v[Cq];
#pragma unroll
        for (int c = 0; c < Cq; c++) v[c] = g[(size_t)c * HWq];

        float4* dst = (float4*)(nf + (size_t)node * Cq);
#pragma unroll
        for (int i = 0; i < 4; i++)
            dst[i] = make_float4(v[4*i], v[4*i+1], v[4*i+2], v[4*i+3]);
        return;
    }

    // ---------------- stencil part ----------------
    const int h  = blockIdx.x;
    const int w0 = threadIdx.x * 2;

    const int hd = (h < Hq - 1) ? h + 1 : h;
    const float* pc = grid + (size_t)h  * Wq;
    const float* pd = grid + (size_t)hd * Wq;

    const int xr = (w0 + 2 < Wq) ? w0 + 2 : Wq - 1;
    const int xl = (w0 > 0)      ? w0 - 1 : 0;

    // per-column forward accumulators: right, down-left, down, down-right
    float r0 = 0, l0 = 0, d0 = 0, g0 = 0;
    float r1 = 0, l1 = 0, d1 = 0, g1 = 0;

#pragma unroll 4
    for (int bc = 0; bc < Bq * Cq; bc++) {
        float2 c = *(const float2*)(pc + w0);
        float2 d = *(const float2*)(pd + w0);
        float cr  = pc[xr];
        float dll = pd[xl];
        float drr = pd[xr];

        r0 += fabsf(c.x - c.y);
        l0 += fabsf(c.x - dll);
        d0 += fabsf(c.x - d.x);
        g0 += fabsf(c.x - d.y);

        r1 += fabsf(c.y - cr);
        l1 += fabsf(c.y - d.x);
        d1 += fabsf(c.y - d.y);
        g1 += fabsf(c.y - drr);

        pc += HWq; pd += HWq;
    }

    const float inv = 1.0f / (float)(Bq * Cq);
    const int n0 = h * Wq + w0;
    // invalid boundary dirs store garbage; K2 never reads them
    *(float4*)&g_scratch[(size_t)n0 * 4] =
        make_float4(r0 * inv, l0 * inv, d0 * inv, g0 * inv);
    *(float4*)&g_scratch[(size_t)(n0 + 1) * 4] =
        make_float4(r1 * inv, l1 * inv, d1 * inv, g1 * inv);
}

// Kernel 2: edge-writer. e -> (h,w,slot,k) analytically; fdiff from the
// owning node's forward slot in g_scratch; dense ei + attr float2 writes.
__global__ void __launch_bounds__(256) k2_edges(
    float* __restrict__ ei_out, float* __restrict__ attr, int E)
{
    int e = blockIdx.x * 256 + threadIdx.x;
    if (e >= E) return;

    int h, r;
    if (e < ROW0_EDGES)          { h = 0;   r = e; }
    else if (e >= LASTROW_BASE)  { h = 511; r = e - LASTROW_BASE; }
    else { int t = e - ROW0_EDGES; h = 1 + t / ROWI_EDGES; r = t % ROWI_EDGES; }

    const bool edgeRow = (h == 0) || (h == Hq - 1);
    int w, slot;
    if (edgeRow) {
        if (r < 3)          { w = 0;      slot = r; }
        else if (r >= 2553) { w = Wq - 1; slot = r - 2553; }
        else                { w = 1 + (r - 3) / 5; slot = (r - 3) % 5; }
    } else {
        if (r < 5)          { w = 0;      slot = r; }
        else if (r >= 4085) { w = Wq - 1; slot = r - 4085; }
        else                { w = 1 + (r - 5) / 8; slot = (r - 5) % 8; }
    }

    const bool up_ok = (h > 0), dn_ok = (h < Hq - 1);
    const bool l_ok = (w > 0),  r_ok  = (w < Wq - 1);
    const bool v[8] = { up_ok && l_ok, up_ok, up_ok && r_ok,
                        l_ok, r_ok,
                        dn_ok && l_ok, dn_ok, dn_ok && r_ok };
    const int   doff[8] = {-Wq - 1, -Wq, -Wq + 1, -1, 1, Wq - 1, Wq, Wq + 1};
    const float dtab[8] = {SQ2f, 1.0f, SQ2f, 1.0f, 1.0f, SQ2f, 1.0f, SQ2f};
    // owner of the forward value for direction k: node n + noff, fwd slot fidx
    const int noff[8] = {-Wq - 1, -Wq, -Wq + 1, -1, 0, 0, 0, 0};
    const int fidx[8] = {3, 2, 1, 0, 0, 1, 2, 3};

    int k = 0, cnt = 0;
#pragma unroll
    for (int kk = 0; kk < 8; kk++) {
        if (v[kk]) { if (cnt == slot) k = kk; cnt++; }
    }

    const int n = h * Wq + w;
    const float fd = g_scratch[(size_t)(n + noff[k]) * 4 + fidx[k]];

    ei_out[e]     = (float)n;
    ei_out[E + e] = (float)(n + doff[k]);
    ((float2*)attr)[e] = make_float2(dtab[k], fd);
}

extern "C" void kernel_launch(void* const* d_in, const int* in_sizes, int n_in,
                              void* d_out, int out_size)
{
    const float* grid = (const float*)d_in[0];
    const int E = in_sizes[1] / 2;

    float* out    = (float*)d_out;
    float* nf     = out;                    // [NODES, C]
    float* ei_out = out + NF_ELEMS;         // [2, E] as float
    float* attr   = ei_out + 2 * (size_t)E; // [E, 2]

    k1_stencil_transpose<<<ATTR_BLOCKS + TRANS_BLOCKS, 256>>>(grid, nf);
    k2_edges<<<EW_BLOCKS, 256>>>(ei_out, attr, E);
}